// round 4
// baseline (speedup 1.0000x reference)
#include <cuda_runtime.h>
#include <cuda_fp16.h>

#define NN 200000
#define EE 6400000
#define FF 128
#define HH 16
#define NBLK 196   // ceil(NN/1024)
#define HB  512    // degree histogram bins

// ---------------- device scratch -------------------------------------------
__device__ int     g_is64;
__device__ int     d_cnt[NN];
__device__ int     d_rowptr[NN];
__device__ int     d_cursor[NN];
__device__ int     d_bsum[NBLK];
__device__ int     g_hist[HB];
__device__ float   d_dis[NN];
__device__ int     d_ord[NN];         // sorted (desc degree) -> orig id
__device__ int     d_srp[NN];         // rowptr gathered into sorted order
__device__ int     d_scn[NN];         // cnt gathered into sorted order
__device__ float   d_sds[NN];         // dis gathered into sorted order
__device__ int     d_srcs[EE];        // CSR column indices (dst-sorted, orig layout)
__device__ uint2   d_hwsA[NN * 4];    // fp16x4 per quad-thread: dis[n]*hw[n]
__device__ uint2   d_hwsB[NN * 4];

// ---------------- fp16 helpers ----------------------------------------------
__device__ __forceinline__ float4 h4_to_f4(uint2 u) {
    __half2 a = *reinterpret_cast<__half2*>(&u.x);
    __half2 b = *reinterpret_cast<__half2*>(&u.y);
    float2 fa = __half22float2(a);
    float2 fb = __half22float2(b);
    return make_float4(fa.x, fa.y, fb.x, fb.y);
}
__device__ __forceinline__ uint2 f4_to_h4(float4 f) {
    __half2 a = __floats2half2_rn(f.x, f.y);
    __half2 b = __floats2half2_rn(f.z, f.w);
    uint2 u;
    u.x = *reinterpret_cast<unsigned*>(&a);
    u.y = *reinterpret_cast<unsigned*>(&b);
    return u;
}

// ---------------- prep -------------------------------------------------------

__global__ void k_init(const int* __restrict__ ei) {
    int i = blockIdx.x * blockDim.x + threadIdx.x;
    if (i < NN) d_cnt[i] = 0;
    if (i < HB) g_hist[i] = 0;
    if (blockIdx.x == 0) {
        if (threadIdx.x == 0) g_is64 = 1;
        __syncthreads();
        if (ei[2 * threadIdx.x + 1] != 0) g_is64 = 0;
    }
}

__global__ void k_count(const void* __restrict__ ei) {
    int e = blockIdx.x * blockDim.x + threadIdx.x;
    if (e >= EE) return;
    int d;
    if (g_is64) d = (int)((const long long*)ei)[(long long)EE + e];
    else        d = ((const int*)ei)[EE + e];
    atomicAdd(&d_cnt[d], 1);
}

// block scan of cnt (exclusive) + dis + degree histogram (desc-bin)
__global__ void k_scan1() {
    __shared__ int sh[1024];
    __shared__ int lh[HB];
    int tid = threadIdx.x;
    for (int b = tid; b < HB; b += 1024) lh[b] = 0;
    int i = blockIdx.x * 1024 + tid;
    int v = (i < NN) ? d_cnt[i] : 0;
    if (i < NN) {
        d_dis[i] = rsqrtf((float)(v + 1));
        int bi = HB - 1 - min(v, HB - 1);     // descending degree
        atomicAdd(&lh[bi], 1);
    }
    sh[tid] = v;
    __syncthreads();
    for (int off = 1; off < 1024; off <<= 1) {
        int t = 0;
        if (tid >= off) t = sh[tid - off];
        __syncthreads();
        sh[tid] += t;
        __syncthreads();
    }
    if (i < NN) d_rowptr[i] = sh[tid] - v;
    if (tid == 1023) d_bsum[blockIdx.x] = sh[1023];
    for (int b = tid; b < HB; b += 1024)
        if (lh[b]) atomicAdd(&g_hist[b], lh[b]);
}

// exclusive scans of the 196 block sums and the 512-bin histogram
__global__ void k_scan2() {
    __shared__ int sh[HB];
    int tid = threadIdx.x;                // 512 threads
    int v = (tid < NBLK) ? d_bsum[tid] : 0;
    sh[tid] = v;
    __syncthreads();
    for (int off = 1; off < HB; off <<= 1) {
        int t = 0;
        if (tid >= off) t = sh[tid - off];
        __syncthreads();
        sh[tid] += t;
        __syncthreads();
    }
    if (tid < NBLK) d_bsum[tid] = sh[tid] - v;
    __syncthreads();
    int h = g_hist[tid];
    sh[tid] = h;
    __syncthreads();
    for (int off = 1; off < HB; off <<= 1) {
        int t = 0;
        if (tid >= off) t = sh[tid - off];
        __syncthreads();
        sh[tid] += t;
        __syncthreads();
    }
    g_hist[tid] = sh[tid] - h;            // exclusive offsets (become cursors)
}

__global__ void k_scan3() {
    int i = blockIdx.x * blockDim.x + threadIdx.x;
    if (i >= NN) return;
    int r = d_rowptr[i] + d_bsum[i >> 10];
    d_rowptr[i] = r;
    d_cursor[i] = r;
}

// counting-sort nodes by descending degree
__global__ void k_sort() {
    int n = blockIdx.x * blockDim.x + threadIdx.x;
    if (n >= NN) return;
    int bi = HB - 1 - min(d_cnt[n], HB - 1);
    int pos = atomicAdd(&g_hist[bi], 1);
    d_ord[pos] = n;
}

// gather metadata into sorted-contiguous arrays
__global__ void k_smeta() {
    int i = blockIdx.x * blockDim.x + threadIdx.x;
    if (i >= NN) return;
    int n = d_ord[i];
    d_srp[i] = d_rowptr[n];
    d_scn[i] = d_cnt[n];
    d_sds[i] = d_dis[n];
}

__global__ void k_scatter(const void* __restrict__ ei) {
    int e = blockIdx.x * blockDim.x + threadIdx.x;
    if (e >= EE) return;
    int s, d;
    if (g_is64) {
        s = (int)((const long long*)ei)[e];
        d = (int)((const long long*)ei)[(long long)EE + e];
    } else {
        s = ((const int*)ei)[e];
        d = ((const int*)ei)[EE + e];
    }
    int pos = atomicAdd(&d_cursor[d], 1);
    d_srcs[pos] = s;
}

// ---------------- layer 0: hws = fp16(dis[n] * (X @ W_in)) -------------------
__global__ __launch_bounds__(256) void k_xw(const float* __restrict__ x,
                                            const float* __restrict__ w,
                                            uint2* __restrict__ hws) {
    __shared__ float  xs[256 * 33];
    __shared__ float4 ws4[FF * 4];
    int tid = threadIdx.x;
    int base = blockIdx.x * 256;

    const float4* wv = (const float4*)w;
    for (int i = tid; i < FF * 4; i += 256) ws4[i] = wv[i];

    int cg = tid & 3;
    int g  = tid >> 2;
    float4 o[4];
    #pragma unroll
    for (int i = 0; i < 4; i++) o[i] = make_float4(0.f, 0.f, 0.f, 0.f);

    for (int kc = 0; kc < 4; kc++) {
        __syncthreads();
        for (int i = tid; i < 256 * 32; i += 256) {
            int r = i >> 5, c = i & 31;
            int n = base + r;
            xs[r * 33 + c] = (n < NN) ? x[n * FF + kc * 32 + c] : 0.f;
        }
        __syncthreads();
        #pragma unroll
        for (int kk = 0; kk < 32; kk++) {
            int k = kc * 32 + kk;
            float4 w4 = ws4[k * 4 + cg];
            #pragma unroll
            for (int i = 0; i < 4; i++) {
                float xv = xs[(g * 4 + i) * 33 + kk];
                o[i].x = fmaf(xv, w4.x, o[i].x);
                o[i].y = fmaf(xv, w4.y, o[i].y);
                o[i].z = fmaf(xv, w4.z, o[i].z);
                o[i].w = fmaf(xv, w4.w, o[i].w);
            }
        }
    }
    #pragma unroll
    for (int i = 0; i < 4; i++) {
        int n = base + g * 4 + i;
        if (n < NN) {
            float ds = d_dis[n];
            hws[n * 4 + cg] = f4_to_h4(make_float4(o[i].x * ds, o[i].y * ds,
                                                   o[i].z * ds, o[i].w * ds));
        }
    }
}

// ---------------- SpMM row accumulation (quad-per-node, fp16 payload) --------
// agg = ds * ( sum_{s in N(n)} hws[s] + hws[norig] )
__device__ __forceinline__ float4 accum_row(const uint2* __restrict__ hws,
                                            int norig, int start, int cnt,
                                            int q, float ds) {
    int end = start + cnt;
    float4 s0 = h4_to_f4(__ldg(hws + norig * 4 + q));   // self term
    float4 s1 = make_float4(0.f, 0.f, 0.f, 0.f);
    int j = start;
    for (; j + 8 <= end; j += 8) {
        int idx[8];
        #pragma unroll
        for (int u = 0; u < 8; u++) idx[u] = __ldg(d_srcs + j + u);
        uint2 raw[8];
        #pragma unroll
        for (int u = 0; u < 8; u++) raw[u] = __ldg(hws + idx[u] * 4 + q);
        #pragma unroll
        for (int u = 0; u < 8; u += 2) {
            float4 v0 = h4_to_f4(raw[u]);
            float4 v1 = h4_to_f4(raw[u + 1]);
            s0.x += v0.x; s0.y += v0.y; s0.z += v0.z; s0.w += v0.w;
            s1.x += v1.x; s1.y += v1.y; s1.z += v1.z; s1.w += v1.w;
        }
    }
    for (; j < end; j++) {
        int i0 = __ldg(d_srcs + j);
        float4 v = h4_to_f4(__ldg(hws + i0 * 4 + q));
        s0.x += v.x; s0.y += v.y; s0.z += v.z; s0.w += v.w;
    }
    return make_float4(ds * (s0.x + s1.x), ds * (s0.y + s1.y),
                       ds * (s0.z + s1.z), ds * (s0.w + s1.w));
}

// SpMM + fused epilogue: h = relu(agg + bias); o = h @ W; hws_out = fp16(ds*o)
__global__ __launch_bounds__(256) void k_spmm_tr(const uint2* __restrict__ hws,
                                                 const float* __restrict__ bias,
                                                 const float* __restrict__ W,
                                                 uint2* __restrict__ hws_out) {
    __shared__ float4 ws4[64];
    __shared__ float  bs[16];
    int tid = threadIdx.x;
    if (tid < 64) ws4[tid] = ((const float4*)W)[tid];
    if (tid < 16) bs[tid] = bias[tid];
    __syncthreads();

    int i = blockIdx.x * 64 + (tid >> 2);     // sorted position
    int q = tid & 3;
    int norig = __ldg(d_ord + i);
    float ds  = __ldg(d_sds + i);
    float4 a = accum_row(hws, norig, __ldg(d_srp + i), __ldg(d_scn + i), q, ds);

    float hq[4];
    hq[0] = fmaxf(a.x + bs[q * 4 + 0], 0.f);
    hq[1] = fmaxf(a.y + bs[q * 4 + 1], 0.f);
    hq[2] = fmaxf(a.z + bs[q * 4 + 2], 0.f);
    hq[3] = fmaxf(a.w + bs[q * 4 + 3], 0.f);

    int lane = tid & 31;
    int qb = lane & ~3;
    float4 o = make_float4(0.f, 0.f, 0.f, 0.f);
    #pragma unroll
    for (int k = 0; k < 16; k++) {
        float hk = __shfl_sync(0xffffffffu, hq[k & 3], qb + (k >> 2));
        float4 w4 = ws4[k * 4 + q];
        o.x = fmaf(hk, w4.x, o.x);
        o.y = fmaf(hk, w4.y, o.y);
        o.z = fmaf(hk, w4.z, o.z);
        o.w = fmaf(hk, w4.w, o.w);
    }
    hws_out[norig * 4 + q] = f4_to_h4(make_float4(o.x * ds, o.y * ds,
                                                  o.z * ds, o.w * ds));
}

// SpMM + relu only (before the output-layer aggregation)
__global__ __launch_bounds__(256) void k_spmm_relu(const uint2* __restrict__ hws,
                                                   const float* __restrict__ bias,
                                                   uint2* __restrict__ hws_out) {
    __shared__ float bs[16];
    int tid = threadIdx.x;
    if (tid < 16) bs[tid] = bias[tid];
    __syncthreads();

    int i = blockIdx.x * 64 + (tid >> 2);
    int q = tid & 3;
    int norig = __ldg(d_ord + i);
    float ds  = __ldg(d_sds + i);
    float4 a = accum_row(hws, norig, __ldg(d_srp + i), __ldg(d_scn + i), q, ds);

    float4 h;
    h.x = fmaxf(a.x + bs[q * 4 + 0], 0.f) * ds;
    h.y = fmaxf(a.y + bs[q * 4 + 1], 0.f) * ds;
    h.z = fmaxf(a.z + bs[q * 4 + 2], 0.f) * ds;
    h.w = fmaxf(a.w + bs[q * 4 + 3], 0.f) * ds;
    hws_out[norig * 4 + q] = f4_to_h4(h);
}

// final SpMM + fused (agg @ W_out + b_out) + log_softmax
__global__ __launch_bounds__(256) void k_spmm_out(const uint2* __restrict__ hws,
                                                  const float* __restrict__ W,
                                                  const float* __restrict__ bias,
                                                  float* __restrict__ out) {
    __shared__ float ws[16 * 40];
    __shared__ float bo[40];
    int tid = threadIdx.x;
    for (int i = tid; i < 16 * 40; i += 256) ws[i] = W[i];
    if (tid < 40) bo[tid] = bias[tid];
    __syncthreads();

    int i = blockIdx.x * 64 + (tid >> 2);
    int q = tid & 3;
    int norig = __ldg(d_ord + i);
    float ds  = __ldg(d_sds + i);
    float4 a = accum_row(hws, norig, __ldg(d_srp + i), __ldg(d_scn + i), q, ds);
    float hq[4] = {a.x, a.y, a.z, a.w};

    int lane = tid & 31;
    int qb = lane & ~3;

    float z[10];
    #pragma unroll
    for (int j = 0; j < 10; j++) z[j] = bo[j * 4 + q];
    #pragma unroll
    for (int k = 0; k < 16; k++) {
        float hk = __shfl_sync(0xffffffffu, hq[k & 3], qb + (k >> 2));
        #pragma unroll
        for (int j = 0; j < 10; j++) {
            z[j] = fmaf(hk, ws[k * 40 + j * 4 + q], z[j]);
        }
    }
    float m = z[0];
    #pragma unroll
    for (int j = 1; j < 10; j++) m = fmaxf(m, z[j]);
    m = fmaxf(m, __shfl_xor_sync(0xffffffffu, m, 1));
    m = fmaxf(m, __shfl_xor_sync(0xffffffffu, m, 2));
    float ssum = 0.f;
    #pragma unroll
    for (int j = 0; j < 10; j++) ssum += __expf(z[j] - m);
    ssum += __shfl_xor_sync(0xffffffffu, ssum, 1);
    ssum += __shfl_xor_sync(0xffffffffu, ssum, 2);
    float lse = m + logf(ssum);
    #pragma unroll
    for (int j = 0; j < 10; j++) {
        out[norig * 40 + j * 4 + q] = z[j] - lse;
    }
}

// ---------------- launch ------------------------------------------------------

extern "C" void kernel_launch(void* const* d_in, const int* in_sizes, int n_in,
                              void* d_out, int out_size) {
    const float* x     = (const float*)d_in[0];
    const float* w_in  = (const float*)d_in[1];
    const float* b_in  = (const float*)d_in[2];
    const float* w_hid = (const float*)d_in[3];
    const float* b_hid = (const float*)d_in[4];
    const float* w_out = (const float*)d_in[5];
    const float* b_out = (const float*)d_in[6];
    const void*  ei    = d_in[7];
    float* outp = (float*)d_out;

    uint2* bufA; cudaGetSymbolAddress((void**)&bufA, d_hwsA);
    uint2* bufB; cudaGetSymbolAddress((void**)&bufB, d_hwsB);

    const int GB_N = (NN + 255) / 256;
    const int GB_E = (EE + 255) / 256;
    const int GS   = NN / 64;            // 3125, exact

    // prep
    k_init<<<GB_N, 256>>>((const int*)ei);
    k_count<<<GB_E, 256>>>(ei);
    k_scan1<<<NBLK, 1024>>>();
    k_scan2<<<1, HB>>>();
    k_scan3<<<GB_N, 256>>>();
    k_sort<<<GB_N, 256>>>();
    k_smeta<<<GB_N, 256>>>();
    k_scatter<<<GB_E, 256>>>(ei);

    // layer 0 dense
    k_xw<<<GB_N, 256>>>(x, w_in, bufA);

    // 8 fused SpMM+transform layers (ping-pong A<->B)
    uint2* cur = bufA;
    uint2* nxt = bufB;
    for (int i = 0; i < 8; i++) {
        const float* bias = (i == 0) ? b_in : (b_hid + (i - 1) * HH);
        k_spmm_tr<<<GS, 256>>>(cur, bias, w_hid + i * HH * HH, nxt);
        uint2* t = cur; cur = nxt; nxt = t;
    }

    // SpMM + relu (pre-output), then final SpMM + W_out + log_softmax
    k_spmm_relu<<<GS, 256>>>(cur, b_hid + 7 * HH, nxt);
    { uint2* t = cur; cur = nxt; nxt = t; }
    k_spmm_out<<<GS, 256>>>(cur, w_out, b_out, outp);
}